// round 2
// baseline (speedup 1.0000x reference)
#include <cuda_runtime.h>
#include <cuda_bf16.h>
#include <cstdint>

#define NN   50000
#define IND  256
#define HID  128
#define OUTD 64

// -------- device scratch (no allocations allowed) --------
__device__ float g_h1[NN * HID];    // x @ W1
__device__ float g_agg1[NN * HID];  // layer-1 aggregation
__device__ float g_h2[NN * OUTD];   // relu(agg1+b1) @ W2
__device__ float g_dinv[NN];
__device__ int   g_deg[NN];

// ---------------- degree / norm ----------------
__global__ void deg_init_kernel(int* __restrict__ deg, int n) {
    int i = blockIdx.x * blockDim.x + threadIdx.x;
    if (i < n) deg[i] = 1;  // self loop
}

__global__ void deg_count_kernel(const int* __restrict__ dst, int* __restrict__ deg, int E) {
    int i = blockIdx.x * blockDim.x + threadIdx.x;
    if (i < E) atomicAdd(&deg[dst[i]], 1);
}

__global__ void dinv_kernel(const int* __restrict__ deg, float* __restrict__ dinv, int n) {
    int i = blockIdx.x * blockDim.x + threadIdx.x;
    if (i < n) dinv[i] = rsqrtf((float)deg[i]);
}

// ---------------- GEMM: C[M,BN] = op(A)[M,K] @ B[K,BN] ----------------
// FUSE: A element read as relu(A + bias[k])   (bias indexed by K)
template<int BM, int BN, int BK, int TM, int TN, bool FUSE>
__global__ __launch_bounds__(256)
void gemm_kernel(const float* __restrict__ A, const float* __restrict__ B,
                 const float* __restrict__ bias, float* __restrict__ C,
                 int M, int K) {
    __shared__ float As[BK][BM];
    __shared__ float Bs[BK][BN];

    const int tid = threadIdx.x;
    const int m0  = blockIdx.x * BM;

    constexpr int TX = BN / TN;         // threads along N
    const int tx = tid % TX;
    const int ty = tid / TX;

    float acc[TM][TN];
#pragma unroll
    for (int i = 0; i < TM; i++)
#pragma unroll
        for (int j = 0; j < TN; j++) acc[i][j] = 0.f;

    for (int k0 = 0; k0 < K; k0 += BK) {
        // ---- load A tile (BM x BK) as float4 along K, store transposed ----
        constexpr int A4 = BM * BK / 4;
#pragma unroll
        for (int f = tid; f < A4; f += 256) {
            int ar  = f / (BK / 4);
            int ac4 = f % (BK / 4);
            float4 v = make_float4(0.f, 0.f, 0.f, 0.f);
            int gm = m0 + ar;
            if (gm < M) {
                v = *(const float4*)(A + (size_t)gm * K + k0 + ac4 * 4);
                if (FUSE) {
                    int kk = k0 + ac4 * 4;
                    v.x = fmaxf(v.x + bias[kk + 0], 0.f);
                    v.y = fmaxf(v.y + bias[kk + 1], 0.f);
                    v.z = fmaxf(v.z + bias[kk + 2], 0.f);
                    v.w = fmaxf(v.w + bias[kk + 3], 0.f);
                }
            }
            As[ac4 * 4 + 0][ar] = v.x;
            As[ac4 * 4 + 1][ar] = v.y;
            As[ac4 * 4 + 2][ar] = v.z;
            As[ac4 * 4 + 3][ar] = v.w;
        }
        // ---- load B tile (BK x BN) ----
        constexpr int B4 = BK * BN / 4;
#pragma unroll
        for (int f = tid; f < B4; f += 256) {
            int br  = f / (BN / 4);
            int bc4 = f % (BN / 4);
            float4 v = *(const float4*)(B + (size_t)(k0 + br) * BN + bc4 * 4);
            *(float4*)&Bs[br][bc4 * 4] = v;
        }
        __syncthreads();

#pragma unroll
        for (int k = 0; k < BK; k++) {
            float a[TM], b[TN];
#pragma unroll
            for (int i = 0; i < TM; i += 4) {
                float4 va = *(const float4*)&As[k][ty * TM + i];
                a[i] = va.x; a[i + 1] = va.y; a[i + 2] = va.z; a[i + 3] = va.w;
            }
#pragma unroll
            for (int j = 0; j < TN; j += 4) {
                float4 vb = *(const float4*)&Bs[k][tx * TN + j];
                b[j] = vb.x; b[j + 1] = vb.y; b[j + 2] = vb.z; b[j + 3] = vb.w;
            }
#pragma unroll
            for (int i = 0; i < TM; i++)
#pragma unroll
                for (int j = 0; j < TN; j++) acc[i][j] = fmaf(a[i], b[j], acc[i][j]);
        }
        __syncthreads();
    }

#pragma unroll
    for (int i = 0; i < TM; i++) {
        int gm = m0 + ty * TM + i;
        if (gm < M) {
#pragma unroll
            for (int j = 0; j < TN; j += 4) {
                *(float4*)(C + (size_t)gm * BN + tx * TN + j) =
                    make_float4(acc[i][j], acc[i][j + 1], acc[i][j + 2], acc[i][j + 3]);
            }
        }
    }
}

// ---------------- self-loop init (also writes every output element) ----------------
// agg1[i][:] = h1[i][:] * dinv[i]^2
__global__ void init_agg1_kernel(const float4* __restrict__ h1, const float* __restrict__ dinv,
                                 float4* __restrict__ agg, int n4) {  // n4 = NN*HID/4
    int i = blockIdx.x * blockDim.x + threadIdx.x;
    if (i >= n4) return;
    int node = i >> 5;  // HID/4 = 32 float4 per row
    float s = dinv[node]; s *= s;
    float4 v = h1[i];
    v.x *= s; v.y *= s; v.z *= s; v.w *= s;
    agg[i] = v;
}

// out[i][:] = h2[i][:] * dinv[i]^2 + b2[:]
__global__ void init_out_kernel(const float2* __restrict__ h2, const float* __restrict__ dinv,
                                const float* __restrict__ b2, float2* __restrict__ out, int n2) {  // NN*OUTD/2
    int i = blockIdx.x * blockDim.x + threadIdx.x;
    if (i >= n2) return;
    int node = i >> 5;           // OUTD/2 = 32 float2 per row
    int c = (i & 31) * 2;
    float s = dinv[node]; s *= s;
    float2 v = h2[i];
    v.x = v.x * s + b2[c];
    v.y = v.y * s + b2[c + 1];
    out[i] = v;
}

// ---------------- edge scatter: one warp per edge ----------------
__global__ void scatter128_kernel(const float* __restrict__ h, const int* __restrict__ src,
                                  const int* __restrict__ dst, const float* __restrict__ dinv,
                                  float* __restrict__ out, int E) {
    long long t = (long long)blockIdx.x * blockDim.x + threadIdx.x;
    int e = (int)(t >> 5);
    if (e >= E) return;
    int lane = threadIdx.x & 31;
    int s = src[e];
    int d = dst[e];
    float nrm = dinv[s] * dinv[d];
    float4 v = *((const float4*)(h + (size_t)s * HID) + lane);  // 32 float4 per row
    float* p = out + (size_t)d * HID + lane * 4;
    asm volatile("red.global.add.v4.f32 [%0], {%1,%2,%3,%4};"
                 :: "l"(p), "f"(v.x * nrm), "f"(v.y * nrm), "f"(v.z * nrm), "f"(v.w * nrm)
                 : "memory");
}

__global__ void scatter64_kernel(const float* __restrict__ h, const int* __restrict__ src,
                                 const int* __restrict__ dst, const float* __restrict__ dinv,
                                 float* __restrict__ out, int E) {
    long long t = (long long)blockIdx.x * blockDim.x + threadIdx.x;
    int e = (int)(t >> 5);
    if (e >= E) return;
    int lane = threadIdx.x & 31;
    int s = src[e];
    int d = dst[e];
    float nrm = dinv[s] * dinv[d];
    float2 v = *((const float2*)(h + (size_t)s * OUTD) + lane);  // 32 float2 per row
    float* p = out + (size_t)d * OUTD + lane * 2;
    asm volatile("red.global.add.v2.f32 [%0], {%1,%2};"
                 :: "l"(p), "f"(v.x * nrm), "f"(v.y * nrm)
                 : "memory");
}

// ---------------- launch ----------------
extern "C" void kernel_launch(void* const* d_in, const int* in_sizes, int n_in,
                              void* d_out, int out_size) {
    const float* x   = (const float*)d_in[0];
    const int*   ei  = (const int*)d_in[1];     // int32! (JAX demotes int64 with x64 disabled)
    const float* W1  = (const float*)d_in[2];
    const float* b1  = (const float*)d_in[3];
    const float* W2  = (const float*)d_in[4];
    const float* b2  = (const float*)d_in[5];
    float*       out = (float*)d_out;

    const int E = in_sizes[1] / 2;
    const int* src = ei;
    const int* dst = ei + E;

    void* p;
    cudaGetSymbolAddress(&p, g_h1);   float* h1   = (float*)p;
    cudaGetSymbolAddress(&p, g_agg1); float* agg1 = (float*)p;
    cudaGetSymbolAddress(&p, g_h2);   float* h2   = (float*)p;
    cudaGetSymbolAddress(&p, g_dinv); float* dinv = (float*)p;
    cudaGetSymbolAddress(&p, g_deg);  int*   deg  = (int*)p;

    // degrees + dinv
    deg_init_kernel<<<(NN + 255) / 256, 256>>>(deg, NN);
    deg_count_kernel<<<(E + 255) / 256, 256>>>(dst, deg, E);
    dinv_kernel<<<(NN + 255) / 256, 256>>>(deg, dinv, NN);

    // layer 1: GEMM (h1 = x @ W1), then self-loop init + edge scatter
    gemm_kernel<128, HID, 16, 8, 8, false><<<(NN + 127) / 128, 256>>>(x, W1, nullptr, h1, NN, IND);
    init_agg1_kernel<<<(NN * (HID / 4) + 255) / 256, 256>>>((const float4*)h1, dinv, (float4*)agg1, NN * (HID / 4));
    scatter128_kernel<<<((long long)E * 32 + 255) / 256, 256>>>(h1, src, dst, dinv, agg1, E);

    // layer 2: GEMM with fused relu(agg1 + b1) on A-load, then self-loop+bias init + scatter into d_out
    gemm_kernel<128, OUTD, 16, 8, 4, true><<<(NN + 127) / 128, 256>>>(agg1, W2, b1, h2, NN, HID);
    init_out_kernel<<<(NN * (OUTD / 2) + 255) / 256, 256>>>((const float2*)h2, dinv, b2, (float2*)out, NN * (OUTD / 2));
    scatter64_kernel<<<((long long)E * 32 + 255) / 256, 256>>>(h2, src, dst, dinv, out, E);
}

// round 3
// speedup vs baseline: 1.2112x; 1.2112x over previous
#include <cuda_runtime.h>
#include <cuda_bf16.h>
#include <cstdint>

#define NN   50000
#define IND  256
#define HID  128
#define OUTD 64
#define EMAX 800000

// -------- device scratch --------
__device__ float g_h1[NN * HID];
__device__ float g_agg1[NN * HID];
__device__ float g_h2[NN * OUTD];
__device__ float g_dinv[NN];
__device__ int   g_deg[NN];
__device__ int   g_rowptr[NN + 1];
__device__ int   g_fill[NN];
__device__ int   g_csrc[EMAX];

// ---------------- degree / norm / CSR ----------------
__global__ void deg_init_kernel(int* __restrict__ deg, int* __restrict__ fill, int n) {
    int i = blockIdx.x * blockDim.x + threadIdx.x;
    if (i < n) { deg[i] = 1; fill[i] = 0; }  // self loop counts in degree
}

__global__ void deg_count_kernel(const int* __restrict__ dst, int* __restrict__ deg, int E) {
    int i = blockIdx.x * blockDim.x + threadIdx.x;
    if (i < E) atomicAdd(&deg[dst[i]], 1);
}

__global__ void dinv_kernel(const int* __restrict__ deg, float* __restrict__ dinv, int n) {
    int i = blockIdx.x * blockDim.x + threadIdx.x;
    if (i < n) dinv[i] = rsqrtf((float)deg[i]);
}

// single-block exclusive scan of (deg[i]-1) -> rowptr  (in-edge counts, self loop excluded)
__global__ void scan_kernel(const int* __restrict__ deg, int* __restrict__ rowptr, int n) {
    __shared__ int wsum[32];
    __shared__ int s_carry;
    const int tid = threadIdx.x;
    const int lane = tid & 31, wid = tid >> 5;
    if (tid == 0) s_carry = 0;
    for (int base = 0; base < n; base += 1024) {
        __syncthreads();
        int carry = s_carry;
        int i = base + tid;
        int v = (i < n) ? (deg[i] - 1) : 0;
        // warp inclusive scan
        int x = v;
#pragma unroll
        for (int d = 1; d < 32; d <<= 1) {
            int y = __shfl_up_sync(0xffffffffu, x, d);
            if (lane >= d) x += y;
        }
        if (lane == 31) wsum[wid] = x;
        __syncthreads();
        if (wid == 0) {
            int y = wsum[lane];
#pragma unroll
            for (int d = 1; d < 32; d <<= 1) {
                int z = __shfl_up_sync(0xffffffffu, y, d);
                if (lane >= d) y += z;
            }
            wsum[lane] = y;
        }
        __syncthreads();
        int incl = x + (wid ? wsum[wid - 1] : 0);
        if (i < n) rowptr[i] = carry + incl - v;
        int btot = wsum[31];
        __syncthreads();
        if (tid == 0) s_carry = carry + btot;
    }
    __syncthreads();
    if (tid == 0) rowptr[n] = s_carry;
}

__global__ void fill_kernel(const int* __restrict__ src, const int* __restrict__ dst,
                            const int* __restrict__ rowptr, int* __restrict__ fill,
                            int* __restrict__ csrc, int E) {
    int i = blockIdx.x * blockDim.x + threadIdx.x;
    if (i >= E) return;
    int d = dst[i];
    int pos = rowptr[d] + atomicAdd(&fill[d], 1);
    csrc[pos] = src[i];
}

// ---------------- GEMM: C[M,BN] = op(A)[M,K] @ B[K,BN], double-buffered ----------------
template<int BM, int BN, int BK, int TM, int TN, bool FUSE>
__global__ __launch_bounds__(256)
void gemm_kernel(const float* __restrict__ A, const float* __restrict__ B,
                 const float* __restrict__ bias, float* __restrict__ C,
                 int M, int K) {
    __shared__ float As[2][BK][BM];
    __shared__ float Bs[2][BK][BN];

    const int tid = threadIdx.x;
    const int m0  = blockIdx.x * BM;

    constexpr int TX = BN / TN;
    const int tx = tid % TX;
    const int ty = tid / TX;

    constexpr int NA = BM * BK / 4 / 256;   // float4 per thread for A tile
    constexpr int NB = BK * BN / 4 / 256;   // float4 per thread for B tile

    float4 ra[NA], rb[NB];

    float acc[TM][TN];
#pragma unroll
    for (int i = 0; i < TM; i++)
#pragma unroll
        for (int j = 0; j < TN; j++) acc[i][j] = 0.f;

    auto loadA = [&](int k0) {
#pragma unroll
        for (int u = 0; u < NA; u++) {
            int f = tid + u * 256;
            int ar  = f / (BK / 4);
            int ac4 = f % (BK / 4);
            float4 v = make_float4(0.f, 0.f, 0.f, 0.f);
            int gm = m0 + ar;
            if (gm < M) {
                v = *(const float4*)(A + (size_t)gm * K + k0 + ac4 * 4);
                if (FUSE) {
                    int kk = k0 + ac4 * 4;
                    v.x = fmaxf(v.x + bias[kk + 0], 0.f);
                    v.y = fmaxf(v.y + bias[kk + 1], 0.f);
                    v.z = fmaxf(v.z + bias[kk + 2], 0.f);
                    v.w = fmaxf(v.w + bias[kk + 3], 0.f);
                }
            }
            ra[u] = v;
        }
    };
    auto loadB = [&](int k0) {
#pragma unroll
        for (int u = 0; u < NB; u++) {
            int f = tid + u * 256;
            int br  = f / (BN / 4);
            int bc4 = f % (BN / 4);
            rb[u] = *(const float4*)(B + (size_t)(k0 + br) * BN + bc4 * 4);
        }
    };
    auto storeTile = [&](int buf) {
#pragma unroll
        for (int u = 0; u < NA; u++) {
            int f = tid + u * 256;
            int ar  = f / (BK / 4);
            int ac4 = f % (BK / 4);
            As[buf][ac4 * 4 + 0][ar] = ra[u].x;
            As[buf][ac4 * 4 + 1][ar] = ra[u].y;
            As[buf][ac4 * 4 + 2][ar] = ra[u].z;
            As[buf][ac4 * 4 + 3][ar] = ra[u].w;
        }
#pragma unroll
        for (int u = 0; u < NB; u++) {
            int f = tid + u * 256;
            int br  = f / (BN / 4);
            int bc4 = f % (BN / 4);
            *(float4*)&Bs[buf][br][bc4 * 4] = rb[u];
        }
    };

    const int nIter = K / BK;
    loadA(0); loadB(0);
    storeTile(0);
    __syncthreads();

    for (int it = 0; it < nIter; ++it) {
        if (it + 1 < nIter) { loadA((it + 1) * BK); loadB((it + 1) * BK); }
        const int p = it & 1;
#pragma unroll
        for (int k = 0; k < BK; k++) {
            float a[TM], b[TN];
#pragma unroll
            for (int i = 0; i < TM; i += 4) {
                float4 va = *(const float4*)&As[p][k][ty * TM + i];
                a[i] = va.x; a[i + 1] = va.y; a[i + 2] = va.z; a[i + 3] = va.w;
            }
#pragma unroll
            for (int j = 0; j < TN; j += 4) {
                float4 vb = *(const float4*)&Bs[p][k][tx * TN + j];
                b[j] = vb.x; b[j + 1] = vb.y; b[j + 2] = vb.z; b[j + 3] = vb.w;
            }
#pragma unroll
            for (int i = 0; i < TM; i++)
#pragma unroll
                for (int j = 0; j < TN; j++) acc[i][j] = fmaf(a[i], b[j], acc[i][j]);
        }
        if (it + 1 < nIter) storeTile((it + 1) & 1);
        __syncthreads();
    }

#pragma unroll
    for (int i = 0; i < TM; i++) {
        int gm = m0 + ty * TM + i;
        if (gm < M) {
#pragma unroll
            for (int j = 0; j < TN; j += 4) {
                *(float4*)(C + (size_t)gm * BN + tx * TN + j) =
                    make_float4(acc[i][j], acc[i][j + 1], acc[i][j + 2], acc[i][j + 3]);
            }
        }
    }
}

// ---------------- CSR gather aggregation: one warp per node ----------------
// agg[d] = dinv[d] * sum_{s in row(d)} dinv[s]*h[s]  +  dinv[d]^2 * h[d]
__global__ void gather128_kernel(const float4* __restrict__ h, const int* __restrict__ csrc,
                                 const int* __restrict__ rowptr, const float* __restrict__ dinv,
                                 float4* __restrict__ out) {
    int w = (blockIdx.x * blockDim.x + threadIdx.x) >> 5;
    if (w >= NN) return;
    int lane = threadIdx.x & 31;
    int begin = rowptr[w], end = rowptr[w + 1];
    float4 acc0 = make_float4(0.f, 0.f, 0.f, 0.f);
    float4 acc1 = make_float4(0.f, 0.f, 0.f, 0.f);
    int j = begin;
    for (; j + 2 <= end; j += 2) {
        int s0 = __ldg(&csrc[j]);
        int s1 = __ldg(&csrc[j + 1]);
        float w0 = __ldg(&dinv[s0]);
        float w1 = __ldg(&dinv[s1]);
        float4 v0 = __ldg(&h[(size_t)s0 * 32 + lane]);
        float4 v1 = __ldg(&h[(size_t)s1 * 32 + lane]);
        acc0.x = fmaf(w0, v0.x, acc0.x); acc0.y = fmaf(w0, v0.y, acc0.y);
        acc0.z = fmaf(w0, v0.z, acc0.z); acc0.w = fmaf(w0, v0.w, acc0.w);
        acc1.x = fmaf(w1, v1.x, acc1.x); acc1.y = fmaf(w1, v1.y, acc1.y);
        acc1.z = fmaf(w1, v1.z, acc1.z); acc1.w = fmaf(w1, v1.w, acc1.w);
    }
    if (j < end) {
        int s0 = __ldg(&csrc[j]);
        float w0 = __ldg(&dinv[s0]);
        float4 v0 = __ldg(&h[(size_t)s0 * 32 + lane]);
        acc0.x = fmaf(w0, v0.x, acc0.x); acc0.y = fmaf(w0, v0.y, acc0.y);
        acc0.z = fmaf(w0, v0.z, acc0.z); acc0.w = fmaf(w0, v0.w, acc0.w);
    }
    float dv = dinv[w];
    float dv2 = dv * dv;
    float4 self = __ldg(&h[(size_t)w * 32 + lane]);
    float4 r;
    r.x = dv * (acc0.x + acc1.x) + dv2 * self.x;
    r.y = dv * (acc0.y + acc1.y) + dv2 * self.y;
    r.z = dv * (acc0.z + acc1.z) + dv2 * self.z;
    r.w = dv * (acc0.w + acc1.w) + dv2 * self.w;
    out[(size_t)w * 32 + lane] = r;
}

// out[d] = dinv[d]*sum + dinv[d]^2*h[d] + b2
__global__ void gather64_kernel(const float2* __restrict__ h, const int* __restrict__ csrc,
                                const int* __restrict__ rowptr, const float* __restrict__ dinv,
                                const float* __restrict__ b2, float2* __restrict__ out) {
    int w = (blockIdx.x * blockDim.x + threadIdx.x) >> 5;
    if (w >= NN) return;
    int lane = threadIdx.x & 31;
    int begin = rowptr[w], end = rowptr[w + 1];
    float2 acc0 = make_float2(0.f, 0.f);
    float2 acc1 = make_float2(0.f, 0.f);
    int j = begin;
    for (; j + 2 <= end; j += 2) {
        int s0 = __ldg(&csrc[j]);
        int s1 = __ldg(&csrc[j + 1]);
        float w0 = __ldg(&dinv[s0]);
        float w1 = __ldg(&dinv[s1]);
        float2 v0 = __ldg(&h[(size_t)s0 * 32 + lane]);
        float2 v1 = __ldg(&h[(size_t)s1 * 32 + lane]);
        acc0.x = fmaf(w0, v0.x, acc0.x); acc0.y = fmaf(w0, v0.y, acc0.y);
        acc1.x = fmaf(w1, v1.x, acc1.x); acc1.y = fmaf(w1, v1.y, acc1.y);
    }
    if (j < end) {
        int s0 = __ldg(&csrc[j]);
        float w0 = __ldg(&dinv[s0]);
        float2 v0 = __ldg(&h[(size_t)s0 * 32 + lane]);
        acc0.x = fmaf(w0, v0.x, acc0.x); acc0.y = fmaf(w0, v0.y, acc0.y);
    }
    float dv = dinv[w];
    float dv2 = dv * dv;
    float2 self = __ldg(&h[(size_t)w * 32 + lane]);
    float2 r;
    r.x = dv * (acc0.x + acc1.x) + dv2 * self.x + b2[lane * 2 + 0];
    r.y = dv * (acc0.y + acc1.y) + dv2 * self.y + b2[lane * 2 + 1];
    out[(size_t)w * 32 + lane] = r;
}

// ---------------- launch ----------------
extern "C" void kernel_launch(void* const* d_in, const int* in_sizes, int n_in,
                              void* d_out, int out_size) {
    const float* x   = (const float*)d_in[0];
    const int*   ei  = (const int*)d_in[1];   // int32 (JAX x64 disabled)
    const float* W1  = (const float*)d_in[2];
    const float* b1  = (const float*)d_in[3];
    const float* W2  = (const float*)d_in[4];
    const float* b2  = (const float*)d_in[5];
    float*       out = (float*)d_out;

    const int E = in_sizes[1] / 2;
    const int* src = ei;
    const int* dst = ei + E;

    void* p;
    cudaGetSymbolAddress(&p, g_h1);     float* h1     = (float*)p;
    cudaGetSymbolAddress(&p, g_agg1);   float* agg1   = (float*)p;
    cudaGetSymbolAddress(&p, g_h2);     float* h2     = (float*)p;
    cudaGetSymbolAddress(&p, g_dinv);   float* dinv   = (float*)p;
    cudaGetSymbolAddress(&p, g_deg);    int*   deg    = (int*)p;
    cudaGetSymbolAddress(&p, g_rowptr); int*   rowptr = (int*)p;
    cudaGetSymbolAddress(&p, g_fill);   int*   fill   = (int*)p;
    cudaGetSymbolAddress(&p, g_csrc);   int*   csrc   = (int*)p;

    // degrees, dinv, CSR
    deg_init_kernel<<<(NN + 255) / 256, 256>>>(deg, fill, NN);
    deg_count_kernel<<<(E + 255) / 256, 256>>>(dst, deg, E);
    dinv_kernel<<<(NN + 255) / 256, 256>>>(deg, dinv, NN);
    scan_kernel<<<1, 1024>>>(deg, rowptr, NN);
    fill_kernel<<<(E + 255) / 256, 256>>>(src, dst, rowptr, fill, csrc, E);

    const int warpsGrid = (NN * 32 + 255) / 256;

    // layer 1
    gemm_kernel<128, HID, 16, 8, 8, false><<<(NN + 127) / 128, 256>>>(x, W1, nullptr, h1, NN, IND);
    gather128_kernel<<<warpsGrid, 256>>>((const float4*)h1, csrc, rowptr, dinv, (float4*)agg1);

    // layer 2 (relu(agg1+b1) fused into GEMM A-load)
    gemm_kernel<128, OUTD, 16, 8, 4, true><<<(NN + 127) / 128, 256>>>(agg1, W2, b1, h2, NN, HID);
    gather64_kernel<<<warpsGrid, 256>>>((const float2*)h2, csrc, rowptr, dinv, b2, (float2*)out);
}

// round 4
// speedup vs baseline: 1.4368x; 1.1863x over previous
#include <cuda_runtime.h>
#include <cuda_bf16.h>
#include <cstdint>

#define NN   50000
#define IND  256
#define HID  128
#define OUTD 64
#define EMAX 800000

// scan config
#define SC_T     256
#define SC_I     16
#define SC_CHUNK (SC_T * SC_I)                       // 4096
#define SC_NB    ((NN + SC_CHUNK - 1) / SC_CHUNK)    // 13

// -------- device scratch --------
__device__ float g_h1[NN * HID];    // dinv-scaled x@W1
__device__ float g_agg1[NN * HID];
__device__ float g_h2[NN * OUTD];   // dinv-scaled relu(agg1+b1)@W2
__device__ float g_dinv[NN];
__device__ int   g_deg[NN];
__device__ int   g_rowptr[NN + 1];
__device__ int   g_fill[NN];
__device__ int   g_csrc[EMAX];
__device__ int   g_bsum[SC_NB];
__device__ int   g_boff[SC_NB];

// ---------------- f32x2 helpers ----------------
__device__ __forceinline__ unsigned long long dup2(float x) {
    unsigned long long r;
    asm("mov.b64 %0, {%1, %1};" : "=l"(r) : "f"(x));
    return r;
}
__device__ __forceinline__ float2 unpk(unsigned long long v) {
    float2 f;
    asm("mov.b64 {%0, %1}, %2;" : "=f"(f.x), "=f"(f.y) : "l"(v));
    return f;
}
#define FFMA2(d, a, b) asm("fma.rn.f32x2 %0, %1, %2, %0;" : "+l"(d) : "l"(a), "l"(b))

// ---------------- degree / norm ----------------
__global__ void deg_init_kernel(int* __restrict__ deg, int* __restrict__ fill, int n) {
    int i = blockIdx.x * blockDim.x + threadIdx.x;
    if (i < n) { deg[i] = 1; fill[i] = 0; }
}

__global__ void deg_count_kernel(const int* __restrict__ dst, int* __restrict__ deg, int E) {
    int i = blockIdx.x * blockDim.x + threadIdx.x;
    if (i < E) atomicAdd(&deg[dst[i]], 1);
}

__global__ void dinv_kernel(const int* __restrict__ deg, float* __restrict__ dinv, int n) {
    int i = blockIdx.x * blockDim.x + threadIdx.x;
    if (i < n) dinv[i] = rsqrtf((float)deg[i]);
}

// ---------------- multi-block exclusive scan of (deg-1) ----------------
__global__ void scan_reduce_kernel(const int* __restrict__ deg, int* __restrict__ bsum, int n) {
    __shared__ int ws[SC_T / 32];
    int b = blockIdx.x, tid = threadIdx.x;
    int base = b * SC_CHUNK + tid * SC_I;
    int s = 0;
#pragma unroll
    for (int u = 0; u < SC_I; u++) {
        int i = base + u;
        if (i < n) s += deg[i] - 1;
    }
#pragma unroll
    for (int d = 16; d; d >>= 1) s += __shfl_down_sync(0xffffffffu, s, d);
    if ((tid & 31) == 0) ws[tid >> 5] = s;
    __syncthreads();
    if (tid < 32) {
        int v = (tid < SC_T / 32) ? ws[tid] : 0;
#pragma unroll
        for (int d = 16; d; d >>= 1) v += __shfl_down_sync(0xffffffffu, v, d);
        if (tid == 0) bsum[b] = v;
    }
}

__global__ void scan_offsets_kernel(const int* __restrict__ bsum, int* __restrict__ boff,
                                    int* __restrict__ rowptr, int n) {
    int lane = threadIdx.x;
    int v = (lane < SC_NB) ? bsum[lane] : 0;
    int x = v;
#pragma unroll
    for (int d = 1; d < 32; d <<= 1) {
        int y = __shfl_up_sync(0xffffffffu, x, d);
        if (lane >= d) x += y;
    }
    if (lane < SC_NB) boff[lane] = x - v;
    if (lane == 31) rowptr[n] = x;
}

__global__ void scan_write_kernel(const int* __restrict__ deg, const int* __restrict__ boff,
                                  int* __restrict__ rowptr, int n) {
    __shared__ int ws[SC_T / 32];
    int b = blockIdx.x, tid = threadIdx.x;
    int lane = tid & 31, wid = tid >> 5;
    int base = b * SC_CHUNK + tid * SC_I;
    int v[SC_I];
    int tot = 0;
#pragma unroll
    for (int u = 0; u < SC_I; u++) {
        int i = base + u;
        int d = (i < n) ? (deg[i] - 1) : 0;
        v[u] = tot;          // local exclusive prefix
        tot += d;
    }
    // block exclusive scan of per-thread totals
    int x = tot;
#pragma unroll
    for (int d = 1; d < 32; d <<= 1) {
        int y = __shfl_up_sync(0xffffffffu, x, d);
        if (lane >= d) x += y;
    }
    if (lane == 31) ws[wid] = x;
    __syncthreads();
    if (wid == 0) {
        int y = (lane < SC_T / 32) ? ws[lane] : 0;
#pragma unroll
        for (int d = 1; d < 32; d <<= 1) {
            int z = __shfl_up_sync(0xffffffffu, y, d);
            if (lane >= d) y += z;
        }
        if (lane < SC_T / 32) ws[lane] = y;
    }
    __syncthreads();
    int off = boff[b] + (x - tot) + (wid ? ws[wid - 1] : 0);
#pragma unroll
    for (int u = 0; u < SC_I; u++) {
        int i = base + u;
        if (i < n) rowptr[i] = off + v[u];
    }
}

__global__ void fill_kernel(const int* __restrict__ src, const int* __restrict__ dst,
                            const int* __restrict__ rowptr, int* __restrict__ fill,
                            int* __restrict__ csrc, int E) {
    int i = blockIdx.x * blockDim.x + threadIdx.x;
    if (i >= E) return;
    int d = dst[i];
    int pos = rowptr[d] + atomicAdd(&fill[d], 1);
    csrc[pos] = src[i];
}

// ---------------- GEMM with packed f32x2 FMA ----------------
// C[gm][:] = rowscale[gm] * (op(A)@B)[gm][:]   (rowscale = dinv, folds GCN norm)
// FUSE: A read as relu(A + bias[k])
template<int BM, int BN, int BK, int TM, int TN, bool FUSE>
__global__ __launch_bounds__(256)
void gemm_kernel(const float* __restrict__ A, const float* __restrict__ B,
                 const float* __restrict__ bias, const float* __restrict__ rowscale,
                 float* __restrict__ C, int M, int K) {
    __shared__ float As[2][BK][BM];
    __shared__ float Bs[2][BK][BN];

    const int tid = threadIdx.x;
    const int m0  = blockIdx.x * BM;

    constexpr int TX = BN / TN;
    const int tx = tid % TX;
    const int ty = tid / TX;

    constexpr int NA = BM * BK / 4 / 256;
    constexpr int NB = BK * BN / 4 / 256;
    float4 ra[NA], rb[NB];

    unsigned long long acc2[TM][TN / 2];
#pragma unroll
    for (int i = 0; i < TM; i++)
#pragma unroll
        for (int j = 0; j < TN / 2; j++) acc2[i][j] = 0ull;

    auto loadA = [&](int k0) {
#pragma unroll
        for (int u = 0; u < NA; u++) {
            int f = tid + u * 256;
            int ar  = f / (BK / 4);
            int ac4 = f % (BK / 4);
            float4 v = make_float4(0.f, 0.f, 0.f, 0.f);
            int gm = m0 + ar;
            if (gm < M) {
                v = *(const float4*)(A + (size_t)gm * K + k0 + ac4 * 4);
                if (FUSE) {
                    int kk = k0 + ac4 * 4;
                    v.x = fmaxf(v.x + bias[kk + 0], 0.f);
                    v.y = fmaxf(v.y + bias[kk + 1], 0.f);
                    v.z = fmaxf(v.z + bias[kk + 2], 0.f);
                    v.w = fmaxf(v.w + bias[kk + 3], 0.f);
                }
            }
            ra[u] = v;
        }
    };
    auto loadB = [&](int k0) {
#pragma unroll
        for (int u = 0; u < NB; u++) {
            int f = tid + u * 256;
            int br  = f / (BN / 4);
            int bc4 = f % (BN / 4);
            rb[u] = *(const float4*)(B + (size_t)(k0 + br) * BN + bc4 * 4);
        }
    };
    auto storeTile = [&](int buf) {
#pragma unroll
        for (int u = 0; u < NA; u++) {
            int f = tid + u * 256;
            int ar  = f / (BK / 4);
            int ac4 = f % (BK / 4);
            As[buf][ac4 * 4 + 0][ar] = ra[u].x;
            As[buf][ac4 * 4 + 1][ar] = ra[u].y;
            As[buf][ac4 * 4 + 2][ar] = ra[u].z;
            As[buf][ac4 * 4 + 3][ar] = ra[u].w;
        }
#pragma unroll
        for (int u = 0; u < NB; u++) {
            int f = tid + u * 256;
            int br  = f / (BN / 4);
            int bc4 = f % (BN / 4);
            *(float4*)&Bs[buf][br][bc4 * 4] = rb[u];
        }
    };

    const int nIter = K / BK;
    loadA(0); loadB(0);
    storeTile(0);
    __syncthreads();

    for (int it = 0; it < nIter; ++it) {
        if (it + 1 < nIter) { loadA((it + 1) * BK); loadB((it + 1) * BK); }
        const int p = it & 1;
#pragma unroll
        for (int k = 0; k < BK; k++) {
            unsigned long long ap[TM];
#pragma unroll
            for (int i = 0; i < TM; i += 4) {
                float4 va = *(const float4*)&As[p][k][ty * TM + i];
                ap[i + 0] = dup2(va.x); ap[i + 1] = dup2(va.y);
                ap[i + 2] = dup2(va.z); ap[i + 3] = dup2(va.w);
            }
            unsigned long long bp[TN / 2];
#pragma unroll
            for (int j = 0; j < TN / 2; j += 2) {
                ulonglong2 vb = *(const ulonglong2*)&Bs[p][k][tx * TN + j * 2];
                bp[j] = vb.x; bp[j + 1] = vb.y;
            }
#pragma unroll
            for (int i = 0; i < TM; i++)
#pragma unroll
                for (int j = 0; j < TN / 2; j++) FFMA2(acc2[i][j], ap[i], bp[j]);
        }
        if (it + 1 < nIter) storeTile((it + 1) & 1);
        __syncthreads();
    }

#pragma unroll
    for (int i = 0; i < TM; i++) {
        int gm = m0 + ty * TM + i;
        if (gm < M) {
            float sc = rowscale[gm];
#pragma unroll
            for (int j = 0; j < TN / 2; j += 2) {
                float2 lo = unpk(acc2[i][j]);
                float2 hi = unpk(acc2[i][j + 1]);
                *(float4*)(C + (size_t)gm * BN + tx * TN + j * 2) =
                    make_float4(lo.x * sc, lo.y * sc, hi.x * sc, hi.y * sc);
            }
        }
    }
}

// ---------------- CSR gather aggregation (inputs pre-scaled by dinv) ----------------
// agg[d] = dinv[d] * ( sum_{s in row(d)} hs[s]  +  hs[d] )
__global__ void gather128_kernel(const float4* __restrict__ hs, const int* __restrict__ csrc,
                                 const int* __restrict__ rowptr, const float* __restrict__ dinv,
                                 float4* __restrict__ out) {
    int w = (blockIdx.x * blockDim.x + threadIdx.x) >> 5;
    if (w >= NN) return;
    int lane = threadIdx.x & 31;
    int begin = rowptr[w], end = rowptr[w + 1];
    float4 a0 = __ldg(&hs[(size_t)w * 32 + lane]);  // self term (already dinv-scaled)
    float4 a1 = make_float4(0.f, 0.f, 0.f, 0.f);
    int j = begin;
    for (; j + 2 <= end; j += 2) {
        int s0 = __ldg(&csrc[j]);
        int s1 = __ldg(&csrc[j + 1]);
        float4 v0 = __ldg(&hs[(size_t)s0 * 32 + lane]);
        float4 v1 = __ldg(&hs[(size_t)s1 * 32 + lane]);
        a0.x += v0.x; a0.y += v0.y; a0.z += v0.z; a0.w += v0.w;
        a1.x += v1.x; a1.y += v1.y; a1.z += v1.z; a1.w += v1.w;
    }
    if (j < end) {
        int s0 = __ldg(&csrc[j]);
        float4 v0 = __ldg(&hs[(size_t)s0 * 32 + lane]);
        a0.x += v0.x; a0.y += v0.y; a0.z += v0.z; a0.w += v0.w;
    }
    float dv = dinv[w];
    float4 r;
    r.x = dv * (a0.x + a1.x);
    r.y = dv * (a0.y + a1.y);
    r.z = dv * (a0.z + a1.z);
    r.w = dv * (a0.w + a1.w);
    out[(size_t)w * 32 + lane] = r;
}

// out[d] = dinv[d]*(sum + hs[d]) + b2
__global__ void gather64_kernel(const float2* __restrict__ hs, const int* __restrict__ csrc,
                                const int* __restrict__ rowptr, const float* __restrict__ dinv,
                                const float* __restrict__ b2, float2* __restrict__ out) {
    int w = (blockIdx.x * blockDim.x + threadIdx.x) >> 5;
    if (w >= NN) return;
    int lane = threadIdx.x & 31;
    int begin = rowptr[w], end = rowptr[w + 1];
    float2 a0 = __ldg(&hs[(size_t)w * 32 + lane]);
    float2 a1 = make_float2(0.f, 0.f);
    int j = begin;
    for (; j + 2 <= end; j += 2) {
        int s0 = __ldg(&csrc[j]);
        int s1 = __ldg(&csrc[j + 1]);
        float2 v0 = __ldg(&hs[(size_t)s0 * 32 + lane]);
        float2 v1 = __ldg(&hs[(size_t)s1 * 32 + lane]);
        a0.x += v0.x; a0.y += v0.y;
        a1.x += v1.x; a1.y += v1.y;
    }
    if (j < end) {
        int s0 = __ldg(&csrc[j]);
        float2 v0 = __ldg(&hs[(size_t)s0 * 32 + lane]);
        a0.x += v0.x; a0.y += v0.y;
    }
    float dv = dinv[w];
    float2 r;
    r.x = dv * (a0.x + a1.x) + b2[lane * 2 + 0];
    r.y = dv * (a0.y + a1.y) + b2[lane * 2 + 1];
    out[(size_t)w * 32 + lane] = r;
}

// ---------------- launch ----------------
extern "C" void kernel_launch(void* const* d_in, const int* in_sizes, int n_in,
                              void* d_out, int out_size) {
    const float* x   = (const float*)d_in[0];
    const int*   ei  = (const int*)d_in[1];   // int32 (JAX x64 disabled)
    const float* W1  = (const float*)d_in[2];
    const float* b1  = (const float*)d_in[3];
    const float* W2  = (const float*)d_in[4];
    const float* b2  = (const float*)d_in[5];
    float*       out = (float*)d_out;

    const int E = in_sizes[1] / 2;
    const int* src = ei;
    const int* dst = ei + E;

    void* p;
    cudaGetSymbolAddress(&p, g_h1);     float* h1     = (float*)p;
    cudaGetSymbolAddress(&p, g_agg1);   float* agg1   = (float*)p;
    cudaGetSymbolAddress(&p, g_h2);     float* h2     = (float*)p;
    cudaGetSymbolAddress(&p, g_dinv);   float* dinv   = (float*)p;
    cudaGetSymbolAddress(&p, g_deg);    int*   deg    = (int*)p;
    cudaGetSymbolAddress(&p, g_rowptr); int*   rowptr = (int*)p;
    cudaGetSymbolAddress(&p, g_fill);   int*   fill   = (int*)p;
    cudaGetSymbolAddress(&p, g_csrc);   int*   csrc   = (int*)p;
    cudaGetSymbolAddress(&p, g_bsum);   int*   bsum   = (int*)p;
    cudaGetSymbolAddress(&p, g_boff);   int*   boff   = (int*)p;

    // degrees, dinv, CSR (multi-block scan)
    deg_init_kernel<<<(NN + 255) / 256, 256>>>(deg, fill, NN);
    deg_count_kernel<<<(E + 255) / 256, 256>>>(dst, deg, E);
    dinv_kernel<<<(NN + 255) / 256, 256>>>(deg, dinv, NN);
    scan_reduce_kernel<<<SC_NB, SC_T>>>(deg, bsum, NN);
    scan_offsets_kernel<<<1, 32>>>(bsum, boff, rowptr, NN);
    scan_write_kernel<<<SC_NB, SC_T>>>(deg, boff, rowptr, NN);
    fill_kernel<<<(E + 255) / 256, 256>>>(src, dst, rowptr, fill, csrc, E);

    const int warpsGrid = (NN * 32 + 255) / 256;

    // layer 1: h1 = dinv * (x @ W1); agg1 = dinv * (sum_in h1 + h1_self)
    gemm_kernel<128, HID, 16, 8, 8, false><<<(NN + 127) / 128, 256>>>(x, W1, nullptr, dinv, h1, NN, IND);
    gather128_kernel<<<warpsGrid, 256>>>((const float4*)h1, csrc, rowptr, dinv, (float4*)agg1);

    // layer 2: h2 = dinv * (relu(agg1+b1) @ W2); out = dinv * (sum_in h2 + h2_self) + b2
    gemm_kernel<128, OUTD, 16, 8, 4, true><<<(NN + 127) / 128, 256>>>(agg1, W2, b1, dinv, h2, NN, HID);
    gather64_kernel<<<warpsGrid, 256>>>((const float2*)h2, csrc, rowptr, dinv, b2, (float2*)out);
}

// round 6
// speedup vs baseline: 1.7942x; 1.2487x over previous
#include <cuda_runtime.h>
#include <cuda_bf16.h>
#include <cstdint>

#define NN   50000
#define IND  256
#define HID  128
#define OUTD 64
#define EMAX 800000

// scan config
#define SC_T     256
#define SC_I     16
#define SC_CHUNK (SC_T * SC_I)
#define SC_NB    ((NN + SC_CHUNK - 1) / SC_CHUNK)

// -------- device scratch --------
__device__ float g_h1[NN * HID];
__device__ float g_agg1[NN * HID];
__device__ float g_h2[NN * OUTD];
__device__ float g_dinv[NN];
__device__ int   g_deg[NN];
__device__ int   g_rowptr[NN + 1];
__device__ int   g_fill[NN];
__device__ int   g_csrc[EMAX];
__device__ int   g_bsum[SC_NB];
__device__ int   g_boff[SC_NB];
// split-precision transposed weights WT[N][K]
__device__ __nv_bfloat16 g_w1hi[HID * IND];
__device__ __nv_bfloat16 g_w1lo[HID * IND];
__device__ __nv_bfloat16 g_w2hi[OUTD * HID];
__device__ __nv_bfloat16 g_w2lo[OUTD * HID];

// ---------------- degree / norm ----------------
__global__ void deg_init_kernel(int* __restrict__ deg, int* __restrict__ fill, int n) {
    int i = blockIdx.x * blockDim.x + threadIdx.x;
    if (i < n) { deg[i] = 1; fill[i] = 0; }
}

__global__ void deg_count_kernel(const int* __restrict__ dst, int* __restrict__ deg, int E) {
    int i = blockIdx.x * blockDim.x + threadIdx.x;
    if (i < E) atomicAdd(&deg[dst[i]], 1);
}

__global__ void dinv_kernel(const int* __restrict__ deg, float* __restrict__ dinv, int n) {
    int i = blockIdx.x * blockDim.x + threadIdx.x;
    if (i < n) dinv[i] = rsqrtf((float)deg[i]);
}

// ---------------- multi-block exclusive scan of (deg-1) ----------------
__global__ void scan_reduce_kernel(const int* __restrict__ deg, int* __restrict__ bsum, int n) {
    __shared__ int ws[SC_T / 32];
    int b = blockIdx.x, tid = threadIdx.x;
    int base = b * SC_CHUNK + tid * SC_I;
    int s = 0;
#pragma unroll
    for (int u = 0; u < SC_I; u++) {
        int i = base + u;
        if (i < n) s += deg[i] - 1;
    }
#pragma unroll
    for (int d = 16; d; d >>= 1) s += __shfl_down_sync(0xffffffffu, s, d);
    if ((tid & 31) == 0) ws[tid >> 5] = s;
    __syncthreads();
    if (tid < 32) {
        int v = (tid < SC_T / 32) ? ws[tid] : 0;
#pragma unroll
        for (int d = 16; d; d >>= 1) v += __shfl_down_sync(0xffffffffu, v, d);
        if (tid == 0) bsum[b] = v;
    }
}

__global__ void scan_offsets_kernel(const int* __restrict__ bsum, int* __restrict__ boff,
                                    int* __restrict__ rowptr, int n) {
    int lane = threadIdx.x;
    int v = (lane < SC_NB) ? bsum[lane] : 0;
    int x = v;
#pragma unroll
    for (int d = 1; d < 32; d <<= 1) {
        int y = __shfl_up_sync(0xffffffffu, x, d);
        if (lane >= d) x += y;
    }
    if (lane < SC_NB) boff[lane] = x - v;
    if (lane == 31) rowptr[n] = x;
}

__global__ void scan_write_kernel(const int* __restrict__ deg, const int* __restrict__ boff,
                                  int* __restrict__ rowptr, int n) {
    __shared__ int ws[SC_T / 32];
    int b = blockIdx.x, tid = threadIdx.x;
    int lane = tid & 31, wid = tid >> 5;
    int base = b * SC_CHUNK + tid * SC_I;
    int v[SC_I];
    int tot = 0;
#pragma unroll
    for (int u = 0; u < SC_I; u++) {
        int i = base + u;
        int d = (i < n) ? (deg[i] - 1) : 0;
        v[u] = tot;
        tot += d;
    }
    int x = tot;
#pragma unroll
    for (int d = 1; d < 32; d <<= 1) {
        int y = __shfl_up_sync(0xffffffffu, x, d);
        if (lane >= d) x += y;
    }
    if (lane == 31) ws[wid] = x;
    __syncthreads();
    if (wid == 0) {
        int y = (lane < SC_T / 32) ? ws[lane] : 0;
#pragma unroll
        for (int d = 1; d < 32; d <<= 1) {
            int z = __shfl_up_sync(0xffffffffu, y, d);
            if (lane >= d) y += z;
        }
        if (lane < SC_T / 32) ws[lane] = y;
    }
    __syncthreads();
    int off = boff[b] + (x - tot) + (wid ? ws[wid - 1] : 0);
#pragma unroll
    for (int u = 0; u < SC_I; u++) {
        int i = base + u;
        if (i < n) rowptr[i] = off + v[u];
    }
}

__global__ void fill_kernel(const int* __restrict__ src, const int* __restrict__ dst,
                            const int* __restrict__ rowptr, int* __restrict__ fill,
                            int* __restrict__ csrc, int E) {
    int i = blockIdx.x * blockDim.x + threadIdx.x;
    if (i >= E) return;
    int d = dst[i];
    int pos = rowptr[d] + atomicAdd(&fill[d], 1);
    csrc[pos] = src[i];
}

// ---------------- weight split + transpose: W[K][N] -> WThi/WTlo[N][K] ----------------
__global__ void wsplit_kernel(const float* __restrict__ W, __nv_bfloat16* __restrict__ Thi,
                              __nv_bfloat16* __restrict__ Tlo, int K, int N) {
    int i = blockIdx.x * blockDim.x + threadIdx.x;
    if (i >= K * N) return;
    int k = i / N, n = i % N;
    float v = W[i];
    __nv_bfloat16 h = __float2bfloat16(v);
    Thi[(size_t)n * K + k] = h;
    Tlo[(size_t)n * K + k] = __float2bfloat16(v - __bfloat162float(h));
}

// ---------------- split-bf16 tensor-core GEMM ----------------
// C[gm][:] = rowscale[gm] * (op(A)@B)[gm][:], op(A)=relu(A+bias[k]) if FUSE
// A fp32 [M][K]; B given as transposed split bf16 WThi/WTlo [BN][K].
#define MMA_BF16(c, a, b) asm volatile( \
    "mma.sync.aligned.m16n8k16.row.col.f32.bf16.bf16.f32 " \
    "{%0,%1,%2,%3}, {%4,%5,%6,%7}, {%8,%9}, {%0,%1,%2,%3};" \
    : "+f"((c)[0]), "+f"((c)[1]), "+f"((c)[2]), "+f"((c)[3]) \
    : "r"((a)[0]), "r"((a)[1]), "r"((a)[2]), "r"((a)[3]), "r"((b)[0]), "r"((b)[1]))

template<int BN, int WGM, int WGN, bool FUSE>
__global__ __launch_bounds__(256)
void mma_gemm_kernel(const float* __restrict__ A,
                     const __nv_bfloat16* __restrict__ BThi,
                     const __nv_bfloat16* __restrict__ BTlo,
                     const float* __restrict__ bias,
                     const float* __restrict__ rowscale,
                     float* __restrict__ C, int M, int K) {
    constexpr int BM = 128, BK = 16, BKP = 20;
    constexpr int MI = BM / (WGM * 16);
    constexpr int NI = BN / (WGN * 8);
    constexpr int NBU = BN * 8 / 256;      // u32 per thread per B matrix per stage

    __shared__ __nv_bfloat16 sAhi[2][BM][BKP], sAlo[2][BM][BKP];
    __shared__ __nv_bfloat16 sBhi[2][BN][BKP], sBlo[2][BN][BKP];

    const int tid  = threadIdx.x;
    const int m0   = blockIdx.x * BM;
    const int w    = tid >> 5, lane = tid & 31;
    const int wm   = (w / WGN) * MI * 16;
    const int wn   = (w % WGN) * NI * 8;
    const int gid  = lane >> 2, tig = lane & 3;

    float4   rA[2];
    uint32_t rBh[NBU], rBl[NBU];

    float acc[MI][NI][4];
#pragma unroll
    for (int i = 0; i < MI; i++)
#pragma unroll
        for (int j = 0; j < NI; j++) {
            acc[i][j][0] = 0.f; acc[i][j][1] = 0.f; acc[i][j][2] = 0.f; acc[i][j][3] = 0.f;
        }

    auto loadA = [&](int k0) {
#pragma unroll
        for (int u = 0; u < 2; u++) {
            int idx = tid + u * 256;     // 512 float4 = 128 rows x 4
            int row = idx >> 2;
            int c4  = idx & 3;
            float4 v = make_float4(0.f, 0.f, 0.f, 0.f);
            int gm = m0 + row;
            if (gm < M) {
                v = *(const float4*)(A + (size_t)gm * K + k0 + c4 * 4);
                if (FUSE) {
                    int kk = k0 + c4 * 4;
                    v.x = fmaxf(v.x + bias[kk + 0], 0.f);
                    v.y = fmaxf(v.y + bias[kk + 1], 0.f);
                    v.z = fmaxf(v.z + bias[kk + 2], 0.f);
                    v.w = fmaxf(v.w + bias[kk + 3], 0.f);
                }
            }
            rA[u] = v;
        }
    };
    auto loadB = [&](int k0) {
#pragma unroll
        for (int u = 0; u < NBU; u++) {
            int idx = tid + u * 256;     // BN*8 u32 = BN rows x 8
            int n = idx >> 3;
            int c = idx & 7;
            rBh[u] = *(const uint32_t*)(BThi + (size_t)n * K + k0 + c * 2);
            rBl[u] = *(const uint32_t*)(BTlo + (size_t)n * K + k0 + c * 2);
        }
    };
    auto storeTile = [&](int buf) {
#pragma unroll
        for (int u = 0; u < 2; u++) {
            int idx = tid + u * 256;
            int row = idx >> 2;
            int c4  = idx & 3;
            float4 v = rA[u];
            __nv_bfloat162 h0 = __floats2bfloat162_rn(v.x, v.y);
            __nv_bfloat162 h1 = __floats2bfloat162_rn(v.z, v.w);
            __nv_bfloat162 l0 = __floats2bfloat162_rn(v.x - __bfloat162float(h0.x),
                                                      v.y - __bfloat162float(h0.y));
            __nv_bfloat162 l1 = __floats2bfloat162_rn(v.z - __bfloat162float(h1.x),
                                                      v.w - __bfloat162float(h1.y));
            *(__nv_bfloat162*)&sAhi[buf][row][c4 * 4]     = h0;
            *(__nv_bfloat162*)&sAhi[buf][row][c4 * 4 + 2] = h1;
            *(__nv_bfloat162*)&sAlo[buf][row][c4 * 4]     = l0;
            *(__nv_bfloat162*)&sAlo[buf][row][c4 * 4 + 2] = l1;
        }
#pragma unroll
        for (int u = 0; u < NBU; u++) {
            int idx = tid + u * 256;
            int n = idx >> 3;
            int c = idx & 7;
            *(uint32_t*)&sBhi[buf][n][c * 2] = rBh[u];
            *(uint32_t*)&sBlo[buf][n][c * 2] = rBl[u];
        }
    };

    const int nIter = K / BK;
    loadA(0); loadB(0);
    storeTile(0);
    __syncthreads();

    for (int it = 0; it < nIter; ++it) {
        if (it + 1 < nIter) { loadA((it + 1) * BK); loadB((it + 1) * BK); }
        const int p = it & 1;

        uint32_t ah[MI][4], al[MI][4];
#pragma unroll
        for (int mi = 0; mi < MI; mi++) {
            int r = wm + mi * 16 + gid;
            ah[mi][0] = *(const uint32_t*)&sAhi[p][r][2 * tig];
            ah[mi][1] = *(const uint32_t*)&sAhi[p][r + 8][2 * tig];
            ah[mi][2] = *(const uint32_t*)&sAhi[p][r][2 * tig + 8];
            ah[mi][3] = *(const uint32_t*)&sAhi[p][r + 8][2 * tig + 8];
            al[mi][0] = *(const uint32_t*)&sAlo[p][r][2 * tig];
            al[mi][1] = *(const uint32_t*)&sAlo[p][r + 8][2 * tig];
            al[mi][2] = *(const uint32_t*)&sAlo[p][r][2 * tig + 8];
            al[mi][3] = *(const uint32_t*)&sAlo[p][r + 8][2 * tig + 8];
        }
        uint32_t bh[NI][2], bl[NI][2];
#pragma unroll
        for (int ni = 0; ni < NI; ni++) {
            int n = wn + ni * 8 + gid;
            bh[ni][0] = *(const uint32_t*)&sBhi[p][n][2 * tig];
            bh[ni][1] = *(const uint32_t*)&sBhi[p][n][2 * tig + 8];
            bl[ni][0] = *(const uint32_t*)&sBlo[p][n][2 * tig];
            bl[ni][1] = *(const uint32_t*)&sBlo[p][n][2 * tig + 8];
        }
#pragma unroll
        for (int mi = 0; mi < MI; mi++)
#pragma unroll
            for (int ni = 0; ni < NI; ni++) {
                MMA_BF16(acc[mi][ni], ah[mi], bh[ni]);
                MMA_BF16(acc[mi][ni], ah[mi], bl[ni]);
                MMA_BF16(acc[mi][ni], al[mi], bh[ni]);
            }

        if (it + 1 < nIter) storeTile((it + 1) & 1);
        __syncthreads();
    }

#pragma unroll
    for (int mi = 0; mi < MI; mi++) {
        int r0 = m0 + wm + mi * 16 + gid;
        int r1 = r0 + 8;
        float s0 = (r0 < M) ? rowscale[r0] : 0.f;
        float s1 = (r1 < M) ? rowscale[r1] : 0.f;
#pragma unroll
        for (int ni = 0; ni < NI; ni++) {
            int col = wn + ni * 8 + 2 * tig;
            if (r0 < M)
                *(float2*)(C + (size_t)r0 * BN + col) =
                    make_float2(acc[mi][ni][0] * s0, acc[mi][ni][1] * s0);
            if (r1 < M)
                *(float2*)(C + (size_t)r1 * BN + col) =
                    make_float2(acc[mi][ni][2] * s1, acc[mi][ni][3] * s1);
        }
    }
}

// ---------------- CSR gather aggregation (inputs pre-scaled by dinv) ----------------
__global__ void gather128_kernel(const float4* __restrict__ hs, const int* __restrict__ csrc,
                                 const int* __restrict__ rowptr, const float* __restrict__ dinv,
                                 float4* __restrict__ out) {
    int w = (blockIdx.x * blockDim.x + threadIdx.x) >> 5;
    if (w >= NN) return;
    int lane = threadIdx.x & 31;
    int begin = rowptr[w], end = rowptr[w + 1];
    float4 a0 = __ldg(&hs[(size_t)w * 32 + lane]);  // self term
    float4 a1 = make_float4(0.f, 0.f, 0.f, 0.f);
    float4 a2 = make_float4(0.f, 0.f, 0.f, 0.f);
    float4 a3 = make_float4(0.f, 0.f, 0.f, 0.f);
    int j = begin;
    for (; j + 4 <= end; j += 4) {
        int s0 = __ldg(&csrc[j]);
        int s1 = __ldg(&csrc[j + 1]);
        int s2 = __ldg(&csrc[j + 2]);
        int s3 = __ldg(&csrc[j + 3]);
        float4 v0 = __ldg(&hs[(size_t)s0 * 32 + lane]);
        float4 v1 = __ldg(&hs[(size_t)s1 * 32 + lane]);
        float4 v2 = __ldg(&hs[(size_t)s2 * 32 + lane]);
        float4 v3 = __ldg(&hs[(size_t)s3 * 32 + lane]);
        a0.x += v0.x; a0.y += v0.y; a0.z += v0.z; a0.w += v0.w;
        a1.x += v1.x; a1.y += v1.y; a1.z += v1.z; a1.w += v1.w;
        a2.x += v2.x; a2.y += v2.y; a2.z += v2.z; a2.w += v2.w;
        a3.x += v3.x; a3.y += v3.y; a3.z += v3.z; a3.w += v3.w;
    }
    for (; j < end; ++j) {
        int s0 = __ldg(&csrc[j]);
        float4 v0 = __ldg(&hs[(size_t)s0 * 32 + lane]);
        a0.x += v0.x; a0.y += v0.y; a0.z += v0.z; a0.w += v0.w;
    }
    float dv = dinv[w];
    float4 r;
    r.x = dv * ((a0.x + a1.x) + (a2.x + a3.x));
    r.y = dv * ((a0.y + a1.y) + (a2.y + a3.y));
    r.z = dv * ((a0.z + a1.z) + (a2.z + a3.z));
    r.w = dv * ((a0.w + a1.w) + (a2.w + a3.w));
    out[(size_t)w * 32 + lane] = r;
}

__global__ void gather64_kernel(const float2* __restrict__ hs, const int* __restrict__ csrc,
                                const int* __restrict__ rowptr, const float* __restrict__ dinv,
                                const float* __restrict__ b2, float2* __restrict__ out) {
    int w = (blockIdx.x * blockDim.x + threadIdx.x) >> 5;
    if (w >= NN) return;
    int lane = threadIdx.x & 31;
    int begin = rowptr[w], end = rowptr[w + 1];
    float2 a0 = __ldg(&hs[(size_t)w * 32 + lane]);
    float2 a1 = make_float2(0.f, 0.f);
    float2 a2 = make_float2(0.f, 0.f);
    float2 a3 = make_float2(0.f, 0.f);
    int j = begin;
    for (; j + 4 <= end; j += 4) {
        int s0 = __ldg(&csrc[j]);
        int s1 = __ldg(&csrc[j + 1]);
        int s2 = __ldg(&csrc[j + 2]);
        int s3 = __ldg(&csrc[j + 3]);
        float2 v0 = __ldg(&hs[(size_t)s0 * 32 + lane]);
        float2 v1 = __ldg(&hs[(size_t)s1 * 32 + lane]);
        float2 v2 = __ldg(&hs[(size_t)s2 * 32 + lane]);
        float2 v3 = __ldg(&hs[(size_t)s3 * 32 + lane]);
        a0.x += v0.x; a0.y += v0.y;
        a1.x += v1.x; a1.y += v1.y;
        a2.x += v2.x; a2.y += v2.y;
        a3.x += v3.x; a3.y += v3.y;
    }
    for (; j < end; ++j) {
        int s0 = __ldg(&csrc[j]);
        float2 v0 = __ldg(&hs[(size_t)s0 * 32 + lane]);
        a0.x += v0.x; a0.y += v0.y;
    }
    float dv = dinv[w];
    float2 r;
    r.x = dv * ((a0.x + a1.x) + (a2.x + a3.x)) + b2[lane * 2 + 0];
    r.y = dv * ((a0.y + a1.y) + (a2.y + a3.y)) + b2[lane * 2 + 1];
    out[(size_t)w * 32 + lane] = r;
}

// ---------------- launch ----------------
extern "C" void kernel_launch(void* const* d_in, const int* in_sizes, int n_in,
                              void* d_out, int out_size) {
    const float* x   = (const float*)d_in[0];
    const int*   ei  = (const int*)d_in[1];   // int32 (JAX x64 disabled)
    const float* W1  = (const float*)d_in[2];
    const float* b1  = (const float*)d_in[3];
    const float* W2  = (const float*)d_in[4];
    const float* b2  = (const float*)d_in[5];
    float*       out = (float*)d_out;

    const int E = in_sizes[1] / 2;
    const int* src = ei;
    const int* dst = ei + E;

    void* p;
    cudaGetSymbolAddress(&p, g_h1);     float* h1     = (float*)p;
    cudaGetSymbolAddress(&p, g_agg1);   float* agg1   = (float*)p;
    cudaGetSymbolAddress(&p, g_h2);     float* h2     = (float*)p;
    cudaGetSymbolAddress(&p, g_dinv);   float* dinv   = (float*)p;
    cudaGetSymbolAddress(&p, g_deg);    int*   deg    = (int*)p;
    cudaGetSymbolAddress(&p, g_rowptr); int*   rowptr = (int*)p;
    cudaGetSymbolAddress(&p, g_fill);   int*   fill   = (int*)p;
    cudaGetSymbolAddress(&p, g_csrc);   int*   csrc   = (int*)p;
    cudaGetSymbolAddress(&p, g_bsum);   int*   bsum   = (int*)p;
    cudaGetSymbolAddress(&p, g_boff);   int*   boff   = (int*)p;
    cudaGetSymbolAddress(&p, g_w1hi);   __nv_bfloat16* w1hi = (__nv_bfloat16*)p;
    cudaGetSymbolAddress(&p, g_w1lo);   __nv_bfloat16* w1lo = (__nv_bfloat16*)p;
    cudaGetSymbolAddress(&p, g_w2hi);   __nv_bfloat16* w2hi = (__nv_bfloat16*)p;
    cudaGetSymbolAddress(&p, g_w2lo);   __nv_bfloat16* w2lo = (__nv_bfloat16*)p;

    // degrees, dinv, CSR
    deg_init_kernel<<<(NN + 255) / 256, 256>>>(deg, fill, NN);
    deg_count_kernel<<<(E + 255) / 256, 256>>>(dst, deg, E);
    dinv_kernel<<<(NN + 255) / 256, 256>>>(deg, dinv, NN);
    scan_reduce_kernel<<<SC_NB, SC_T>>>(deg, bsum, NN);
    scan_offsets_kernel<<<1, 32>>>(bsum, boff, rowptr, NN);
    scan_write_kernel<<<SC_NB, SC_T>>>(deg, boff, rowptr, NN);
    fill_kernel<<<(E + 255) / 256, 256>>>(src, dst, rowptr, fill, csrc, E);

    // weight split+transpose
    wsplit_kernel<<<(IND * HID + 255) / 256, 256>>>(W1, w1hi, w1lo, IND, HID);
    wsplit_kernel<<<(HID * OUTD + 255) / 256, 256>>>(W2, w2hi, w2lo, HID, OUTD);

    const int warpsGrid = (NN * 32 + 255) / 256;
    const int gemmGrid  = (NN + 127) / 128;

    // layer 1: h1 = dinv * (x @ W1)
    mma_gemm_kernel<HID, 2, 4, false><<<gemmGrid, 256>>>(x, w1hi, w1lo, nullptr, dinv, h1, NN, IND);
    gather128_kernel<<<warpsGrid, 256>>>((const float4*)h1, csrc, rowptr, dinv, (float4*)agg1);

    // layer 2: h2 = dinv * (relu(agg1+b1) @ W2)
    mma_gemm_kernel<OUTD, 4, 2, true><<<gemmGrid, 256>>>(agg1, w2hi, w2lo, b1, dinv, h2, NN, HID);
    gather64_kernel<<<warpsGrid, 256>>>((const float2*)h2, csrc, rowptr, dinv, b2, (float2*)out);
}

// round 7
// speedup vs baseline: 1.9912x; 1.1098x over previous
#include <cuda_runtime.h>
#include <cuda_bf16.h>
#include <cstdint>

#define NN   50000
#define IND  256
#define HID  128
#define OUTD 64
#define EMAX 800000

// scan config
#define SC_T     256
#define SC_I     16
#define SC_CHUNK (SC_T * SC_I)
#define SC_NB    ((NN + SC_CHUNK - 1) / SC_CHUNK)

// -------- device scratch --------
__device__ float g_h1[NN * HID];
__device__ float g_agg1[NN * HID];
__device__ float g_h2[NN * OUTD];
__device__ float g_dinv[NN];
__device__ int   g_deg[NN];
__device__ int   g_rowptr[NN + 1];
__device__ int   g_fill[NN];
__device__ int   g_csrc[EMAX];
__device__ int   g_bsum[SC_NB];
__device__ int   g_boff[SC_NB];
__device__ __nv_bfloat16 g_w1hi[HID * IND];
__device__ __nv_bfloat16 g_w1lo[HID * IND];
__device__ __nv_bfloat16 g_w2hi[OUTD * HID];
__device__ __nv_bfloat16 g_w2lo[OUTD * HID];

// ---------------- degree ----------------
__global__ void deg_init_kernel(int* __restrict__ deg, int n) {
    int i = blockIdx.x * blockDim.x + threadIdx.x;
    if (i < n) deg[i] = 1;
}

__global__ void deg_count_kernel(const int* __restrict__ dst, int* __restrict__ deg, int E) {
    int i = blockIdx.x * blockDim.x + threadIdx.x;
    if (i < E) atomicAdd(&deg[dst[i]], 1);
}

// ---------------- scan chain (coalesced) ----------------
// block sums of (deg-1), plus dinv = rsqrt(deg)
__global__ void scan_reduce_kernel(const int* __restrict__ deg, int* __restrict__ bsum,
                                   float* __restrict__ dinv, int n) {
    __shared__ int ws[SC_T / 32];
    int b = blockIdx.x, tid = threadIdx.x;
    int base = b * SC_CHUNK;
    int s = 0;
#pragma unroll
    for (int u = 0; u < SC_I; u++) {
        int i = base + u * SC_T + tid;     // warp-coalesced
        if (i < n) {
            int d = deg[i];
            s += d - 1;
            dinv[i] = rsqrtf((float)d);
        }
    }
#pragma unroll
    for (int d = 16; d; d >>= 1) s += __shfl_down_sync(0xffffffffu, s, d);
    if ((tid & 31) == 0) ws[tid >> 5] = s;
    __syncthreads();
    if (tid < 32) {
        int v = (tid < SC_T / 32) ? ws[tid] : 0;
#pragma unroll
        for (int d = 16; d; d >>= 1) v += __shfl_down_sync(0xffffffffu, v, d);
        if (tid == 0) bsum[b] = v;
    }
}

__global__ void scan_offsets_kernel(const int* __restrict__ bsum, int* __restrict__ boff,
                                    int* __restrict__ rowptr, int n) {
    int lane = threadIdx.x;
    int v = (lane < SC_NB) ? bsum[lane] : 0;
    int x = v;
#pragma unroll
    for (int d = 1; d < 32; d <<= 1) {
        int y = __shfl_up_sync(0xffffffffu, x, d);
        if (lane >= d) x += y;
    }
    if (lane < SC_NB) boff[lane] = x - v;
    if (lane == 31) rowptr[n] = x;
}

// writes rowptr AND fill (= rowptr copy for atomic cursor use)
__global__ void scan_write_kernel(const int* __restrict__ deg, const int* __restrict__ boff,
                                  int* __restrict__ rowptr, int* __restrict__ fill, int n) {
    __shared__ int sbuf[SC_CHUNK];
    __shared__ int ws[SC_T / 32];
    int b = blockIdx.x, tid = threadIdx.x;
    int lane = tid & 31, wid = tid >> 5;
    int base = b * SC_CHUNK;

    // coalesced stage-in
#pragma unroll
    for (int u = 0; u < SC_I; u++) {
        int i = base + u * SC_T + tid;
        sbuf[u * SC_T + tid] = (i < n) ? (deg[i] - 1) : 0;
    }
    __syncthreads();

    // per-thread local exclusive prefix over contiguous SC_I chunk
    int v[SC_I];
    int tot = 0;
#pragma unroll
    for (int u = 0; u < SC_I; u++) {
        int d = sbuf[tid * SC_I + u];
        v[u] = tot;
        tot += d;
    }
    // block exclusive scan of per-thread totals
    int x = tot;
#pragma unroll
    for (int d = 1; d < 32; d <<= 1) {
        int y = __shfl_up_sync(0xffffffffu, x, d);
        if (lane >= d) x += y;
    }
    if (lane == 31) ws[wid] = x;
    __syncthreads();
    if (wid == 0) {
        int y = (lane < SC_T / 32) ? ws[lane] : 0;
#pragma unroll
        for (int d = 1; d < 32; d <<= 1) {
            int z = __shfl_up_sync(0xffffffffu, y, d);
            if (lane >= d) y += z;
        }
        if (lane < SC_T / 32) ws[lane] = y;
    }
    __syncthreads();
    int off = boff[b] + (x - tot) + (wid ? ws[wid - 1] : 0);
#pragma unroll
    for (int u = 0; u < SC_I; u++) sbuf[tid * SC_I + u] = off + v[u];
    __syncthreads();

    // coalesced stage-out to both arrays
#pragma unroll
    for (int u = 0; u < SC_I; u++) {
        int i = base + u * SC_T + tid;
        if (i < n) {
            int r = sbuf[u * SC_T + tid];
            rowptr[i] = r;
            fill[i] = r;
        }
    }
}

__global__ void fill_kernel(const int* __restrict__ src, const int* __restrict__ dst,
                            int* __restrict__ fill, int* __restrict__ csrc, int E) {
    int i = blockIdx.x * blockDim.x + threadIdx.x;
    if (i >= E) return;
    int pos = atomicAdd(&fill[dst[i]], 1);
    csrc[pos] = src[i];
}

// ---------------- combined weight split + transpose ----------------
// W[K][N] -> Thi/Tlo[N][K] for both layers in one launch
__global__ void wsplit_both_kernel(const float* __restrict__ W1, const float* __restrict__ W2,
                                   __nv_bfloat16* __restrict__ T1h, __nv_bfloat16* __restrict__ T1l,
                                   __nv_bfloat16* __restrict__ T2h, __nv_bfloat16* __restrict__ T2l) {
    int i = blockIdx.x * blockDim.x + threadIdx.x;
    const int n1 = IND * HID;
    const int n2 = HID * OUTD;
    if (i < n1) {
        int k = i / HID, n = i % HID;
        float v = W1[i];
        __nv_bfloat16 h = __float2bfloat16(v);
        T1h[(size_t)n * IND + k] = h;
        T1l[(size_t)n * IND + k] = __float2bfloat16(v - __bfloat162float(h));
    } else if (i < n1 + n2) {
        int j = i - n1;
        int k = j / OUTD, n = j % OUTD;
        float v = W2[j];
        __nv_bfloat16 h = __float2bfloat16(v);
        T2h[(size_t)n * HID + k] = h;
        T2l[(size_t)n * HID + k] = __float2bfloat16(v - __bfloat162float(h));
    }
}

// ---------------- split-bf16 tensor-core GEMM ----------------
#define MMA_BF16(c, a, b) asm volatile( \
    "mma.sync.aligned.m16n8k16.row.col.f32.bf16.bf16.f32 " \
    "{%0,%1,%2,%3}, {%4,%5,%6,%7}, {%8,%9}, {%0,%1,%2,%3};" \
    : "+f"((c)[0]), "+f"((c)[1]), "+f"((c)[2]), "+f"((c)[3]) \
    : "r"((a)[0]), "r"((a)[1]), "r"((a)[2]), "r"((a)[3]), "r"((b)[0]), "r"((b)[1]))

template<int BN, int WGM, int WGN, bool FUSE>
__global__ __launch_bounds__(256)
void mma_gemm_kernel(const float* __restrict__ A,
                     const __nv_bfloat16* __restrict__ BThi,
                     const __nv_bfloat16* __restrict__ BTlo,
                     const float* __restrict__ bias,
                     const float* __restrict__ rowscale,
                     float* __restrict__ C, int M, int K) {
    constexpr int BM = 128, BK = 16, BKP = 20;
    constexpr int MI = BM / (WGM * 16);
    constexpr int NI = BN / (WGN * 8);
    constexpr int NBU = BN * 8 / 256;

    __shared__ __nv_bfloat16 sAhi[2][BM][BKP], sAlo[2][BM][BKP];
    __shared__ __nv_bfloat16 sBhi[2][BN][BKP], sBlo[2][BN][BKP];

    const int tid  = threadIdx.x;
    const int m0   = blockIdx.x * BM;
    const int w    = tid >> 5, lane = tid & 31;
    const int wm   = (w / WGN) * MI * 16;
    const int wn   = (w % WGN) * NI * 8;
    const int gid  = lane >> 2, tig = lane & 3;

    float4   rA[2];
    uint32_t rBh[NBU], rBl[NBU];

    float acc[MI][NI][4];
#pragma unroll
    for (int i = 0; i < MI; i++)
#pragma unroll
        for (int j = 0; j < NI; j++) {
            acc[i][j][0] = 0.f; acc[i][j][1] = 0.f; acc[i][j][2] = 0.f; acc[i][j][3] = 0.f;
        }

    auto loadA = [&](int k0) {
#pragma unroll
        for (int u = 0; u < 2; u++) {
            int idx = tid + u * 256;
            int row = idx >> 2;
            int c4  = idx & 3;
            float4 v = make_float4(0.f, 0.f, 0.f, 0.f);
            int gm = m0 + row;
            if (gm < M) {
                v = *(const float4*)(A + (size_t)gm * K + k0 + c4 * 4);
                if (FUSE) {
                    int kk = k0 + c4 * 4;
                    v.x = fmaxf(v.x + bias[kk + 0], 0.f);
                    v.y = fmaxf(v.y + bias[kk + 1], 0.f);
                    v.z = fmaxf(v.z + bias[kk + 2], 0.f);
                    v.w = fmaxf(v.w + bias[kk + 3], 0.f);
                }
            }
            rA[u] = v;
        }
    };
    auto loadB = [&](int k0) {
#pragma unroll
        for (int u = 0; u < NBU; u++) {
            int idx = tid + u * 256;
            int n = idx >> 3;
            int c = idx & 7;
            rBh[u] = *(const uint32_t*)(BThi + (size_t)n * K + k0 + c * 2);
            rBl[u] = *(const uint32_t*)(BTlo + (size_t)n * K + k0 + c * 2);
        }
    };
    auto storeTile = [&](int buf) {
#pragma unroll
        for (int u = 0; u < 2; u++) {
            int idx = tid + u * 256;
            int row = idx >> 2;
            int c4  = idx & 3;
            float4 v = rA[u];
            __nv_bfloat162 h0 = __floats2bfloat162_rn(v.x, v.y);
            __nv_bfloat162 h1 = __floats2bfloat162_rn(v.z, v.w);
            __nv_bfloat162 l0 = __floats2bfloat162_rn(v.x - __bfloat162float(h0.x),
                                                      v.y - __bfloat162float(h0.y));
            __nv_bfloat162 l1 = __floats2bfloat162_rn(v.z - __bfloat162float(h1.x),
                                                      v.w - __bfloat162float(h1.y));
            *(__nv_bfloat162*)&sAhi[buf][row][c4 * 4]     = h0;
            *(__nv_bfloat162*)&sAhi[buf][row][c4 * 4 + 2] = h1;
            *(__nv_bfloat162*)&sAlo[buf][row][c4 * 4]     = l0;
            *(__nv_bfloat162*)&sAlo[buf][row][c4 * 4 + 2] = l1;
        }
#pragma unroll
        for (int u = 0; u < NBU; u++) {
            int idx = tid + u * 256;
            int n = idx >> 3;
            int c = idx & 7;
            *(uint32_t*)&sBhi[buf][n][c * 2] = rBh[u];
            *(uint32_t*)&sBlo[buf][n][c * 2] = rBl[u];
        }
    };

    const int nIter = K / BK;
    loadA(0); loadB(0);
    storeTile(0);
    __syncthreads();

    for (int it = 0; it < nIter; ++it) {
        if (it + 1 < nIter) { loadA((it + 1) * BK); loadB((it + 1) * BK); }
        const int p = it & 1;

        uint32_t ah[MI][4], al[MI][4];
#pragma unroll
        for (int mi = 0; mi < MI; mi++) {
            int r = wm + mi * 16 + gid;
            ah[mi][0] = *(const uint32_t*)&sAhi[p][r][2 * tig];
            ah[mi][1] = *(const uint32_t*)&sAhi[p][r + 8][2 * tig];
            ah[mi][2] = *(const uint32_t*)&sAhi[p][r][2 * tig + 8];
            ah[mi][3] = *(const uint32_t*)&sAhi[p][r + 8][2 * tig + 8];
            al[mi][0] = *(const uint32_t*)&sAlo[p][r][2 * tig];
            al[mi][1] = *(const uint32_t*)&sAlo[p][r + 8][2 * tig];
            al[mi][2] = *(const uint32_t*)&sAlo[p][r][2 * tig + 8];
            al[mi][3] = *(const uint32_t*)&sAlo[p][r + 8][2 * tig + 8];
        }
        uint32_t bh[NI][2], bl[NI][2];
#pragma unroll
        for (int ni = 0; ni < NI; ni++) {
            int n = wn + ni * 8 + gid;
            bh[ni][0] = *(const uint32_t*)&sBhi[p][n][2 * tig];
            bh[ni][1] = *(const uint32_t*)&sBhi[p][n][2 * tig + 8];
            bl[ni][0] = *(const uint32_t*)&sBlo[p][n][2 * tig];
            bl[ni][1] = *(const uint32_t*)&sBlo[p][n][2 * tig + 8];
        }
#pragma unroll
        for (int mi = 0; mi < MI; mi++)
#pragma unroll
            for (int ni = 0; ni < NI; ni++) {
                MMA_BF16(acc[mi][ni], ah[mi], bh[ni]);
                MMA_BF16(acc[mi][ni], ah[mi], bl[ni]);
                MMA_BF16(acc[mi][ni], al[mi], bh[ni]);
            }

        if (it + 1 < nIter) storeTile((it + 1) & 1);
        __syncthreads();
    }

#pragma unroll
    for (int mi = 0; mi < MI; mi++) {
        int r0 = m0 + wm + mi * 16 + gid;
        int r1 = r0 + 8;
        float s0 = (r0 < M) ? rowscale[r0] : 0.f;
        float s1 = (r1 < M) ? rowscale[r1] : 0.f;
#pragma unroll
        for (int ni = 0; ni < NI; ni++) {
            int col = wn + ni * 8 + 2 * tig;
            if (r0 < M)
                *(float2*)(C + (size_t)r0 * BN + col) =
                    make_float2(acc[mi][ni][0] * s0, acc[mi][ni][1] * s0);
            if (r1 < M)
                *(float2*)(C + (size_t)r1 * BN + col) =
                    make_float2(acc[mi][ni][2] * s1, acc[mi][ni][3] * s1);
        }
    }
}

// ---------------- CSR gather aggregation (inputs pre-scaled by dinv) ----------------
__global__ void gather128_kernel(const float4* __restrict__ hs, const int* __restrict__ csrc,
                                 const int* __restrict__ rowptr, const float* __restrict__ dinv,
                                 float4* __restrict__ out) {
    int w = (blockIdx.x * blockDim.x + threadIdx.x) >> 5;
    if (w >= NN) return;
    int lane = threadIdx.x & 31;
    int begin = rowptr[w], end = rowptr[w + 1];
    float4 a0 = __ldg(&hs[(size_t)w * 32 + lane]);
    float4 a1 = make_float4(0.f, 0.f, 0.f, 0.f);
    float4 a2 = make_float4(0.f, 0.f, 0.f, 0.f);
    float4 a3 = make_float4(0.f, 0.f, 0.f, 0.f);
    int j = begin;
    for (; j + 4 <= end; j += 4) {
        int s0 = __ldg(&csrc[j]);
        int s1 = __ldg(&csrc[j + 1]);
        int s2 = __ldg(&csrc[j + 2]);
        int s3 = __ldg(&csrc[j + 3]);
        float4 v0 = __ldg(&hs[(size_t)s0 * 32 + lane]);
        float4 v1 = __ldg(&hs[(size_t)s1 * 32 + lane]);
        float4 v2 = __ldg(&hs[(size_t)s2 * 32 + lane]);
        float4 v3 = __ldg(&hs[(size_t)s3 * 32 + lane]);
        a0.x += v0.x; a0.y += v0.y; a0.z += v0.z; a0.w += v0.w;
        a1.x += v1.x; a1.y += v1.y; a1.z += v1.z; a1.w += v1.w;
        a2.x += v2.x; a2.y += v2.y; a2.z += v2.z; a2.w += v2.w;
        a3.x += v3.x; a3.y += v3.y; a3.z += v3.z; a3.w += v3.w;
    }
    for (; j < end; ++j) {
        int s0 = __ldg(&csrc[j]);
        float4 v0 = __ldg(&hs[(size_t)s0 * 32 + lane]);
        a0.x += v0.x; a0.y += v0.y; a0.z += v0.z; a0.w += v0.w;
    }
    float dv = dinv[w];
    float4 r;
    r.x = dv * ((a0.x + a1.x) + (a2.x + a3.x));
    r.y = dv * ((a0.y + a1.y) + (a2.y + a3.y));
    r.z = dv * ((a0.z + a1.z) + (a2.z + a3.z));
    r.w = dv * ((a0.w + a1.w) + (a2.w + a3.w));
    out[(size_t)w * 32 + lane] = r;
}

__global__ void gather64_kernel(const float2* __restrict__ hs, const int* __restrict__ csrc,
                                const int* __restrict__ rowptr, const float* __restrict__ dinv,
                                const float* __restrict__ b2, float2* __restrict__ out) {
    int w = (blockIdx.x * blockDim.x + threadIdx.x) >> 5;
    if (w >= NN) return;
    int lane = threadIdx.x & 31;
    int begin = rowptr[w], end = rowptr[w + 1];
    float2 a0 = __ldg(&hs[(size_t)w * 32 + lane]);
    float2 a1 = make_float2(0.f, 0.f);
    float2 a2 = make_float2(0.f, 0.f);
    float2 a3 = make_float2(0.f, 0.f);
    int j = begin;
    for (; j + 4 <= end; j += 4) {
        int s0 = __ldg(&csrc[j]);
        int s1 = __ldg(&csrc[j + 1]);
        int s2 = __ldg(&csrc[j + 2]);
        int s3 = __ldg(&csrc[j + 3]);
        float2 v0 = __ldg(&hs[(size_t)s0 * 32 + lane]);
        float2 v1 = __ldg(&hs[(size_t)s1 * 32 + lane]);
        float2 v2 = __ldg(&hs[(size_t)s2 * 32 + lane]);
        float2 v3 = __ldg(&hs[(size_t)s3 * 32 + lane]);
        a0.x += v0.x; a0.y += v0.y;
        a1.x += v1.x; a1.y += v1.y;
        a2.x += v2.x; a2.y += v2.y;
        a3.x += v3.x; a3.y += v3.y;
    }
    for (; j < end; ++j) {
        int s0 = __ldg(&csrc[j]);
        float2 v0 = __ldg(&hs[(size_t)s0 * 32 + lane]);
        a0.x += v0.x; a0.y += v0.y;
    }
    float dv = dinv[w];
    float2 r;
    r.x = dv * ((a0.x + a1.x) + (a2.x + a3.x)) + b2[lane * 2 + 0];
    r.y = dv * ((a0.y + a1.y) + (a2.y + a3.y)) + b2[lane * 2 + 1];
    out[(size_t)w * 32 + lane] = r;
}

// ---------------- launch ----------------
extern "C" void kernel_launch(void* const* d_in, const int* in_sizes, int n_in,
                              void* d_out, int out_size) {
    const float* x   = (const float*)d_in[0];
    const int*   ei  = (const int*)d_in[1];   // int32 (JAX x64 disabled)
    const float* W1  = (const float*)d_in[2];
    const float* b1  = (const float*)d_in[3];
    const float* W2  = (const float*)d_in[4];
    const float* b2  = (const float*)d_in[5];
    float*       out = (float*)d_out;

    const int E = in_sizes[1] / 2;
    const int* src = ei;
    const int* dst = ei + E;

    void* p;
    cudaGetSymbolAddress(&p, g_h1);     float* h1     = (float*)p;
    cudaGetSymbolAddress(&p, g_agg1);   float* agg1   = (float*)p;
    cudaGetSymbolAddress(&p, g_h2);     float* h2     = (float*)p;
    cudaGetSymbolAddress(&p, g_dinv);   float* dinv   = (float*)p;
    cudaGetSymbolAddress(&p, g_deg);    int*   deg    = (int*)p;
    cudaGetSymbolAddress(&p, g_rowptr); int*   rowptr = (int*)p;
    cudaGetSymbolAddress(&p, g_fill);   int*   fill   = (int*)p;
    cudaGetSymbolAddress(&p, g_csrc);   int*   csrc   = (int*)p;
    cudaGetSymbolAddress(&p, g_bsum);   int*   bsum   = (int*)p;
    cudaGetSymbolAddress(&p, g_boff);   int*   boff   = (int*)p;
    cudaGetSymbolAddress(&p, g_w1hi);   __nv_bfloat16* w1hi = (__nv_bfloat16*)p;
    cudaGetSymbolAddress(&p, g_w1lo);   __nv_bfloat16* w1lo = (__nv_bfloat16*)p;
    cudaGetSymbolAddress(&p, g_w2hi);   __nv_bfloat16* w2hi = (__nv_bfloat16*)p;
    cudaGetSymbolAddress(&p, g_w2lo);   __nv_bfloat16* w2lo = (__nv_bfloat16*)p;

    // one-time side-channel objects (no device memory involved)
    static cudaStream_t s1 = nullptr;
    static cudaEvent_t  eFork = nullptr, eDinv = nullptr, eGemm1 = nullptr;
    if (!s1) {
        cudaStreamCreateWithFlags(&s1, cudaStreamNonBlocking);
        cudaEventCreateWithFlags(&eFork,  cudaEventDisableTiming);
        cudaEventCreateWithFlags(&eDinv,  cudaEventDisableTiming);
        cudaEventCreateWithFlags(&eGemm1, cudaEventDisableTiming);
    }

    const int warpsGrid = (NN * 32 + 255) / 256;
    const int gemmGrid  = (NN + 127) / 128;
    const int wsplitN   = IND * HID + HID * OUTD;

    // ---- fork: weight split runs on s1 immediately ----
    cudaEventRecord(eFork, 0);
    cudaStreamWaitEvent(s1, eFork, 0);
    wsplit_both_kernel<<<(wsplitN + 255) / 256, 256, 0, s1>>>(W1, W2, w1hi, w1lo, w2hi, w2lo);

    // ---- main: degree + dinv ----
    deg_init_kernel<<<(NN + 255) / 256, 256>>>(deg, NN);
    deg_count_kernel<<<(E + 255) / 256, 256>>>(dst, deg, E);
    scan_reduce_kernel<<<SC_NB, SC_T>>>(deg, bsum, dinv, NN);
    cudaEventRecord(eDinv, 0);

    // ---- s1: GEMM1 (needs x, W1 split, dinv) overlaps with CSR build ----
    cudaStreamWaitEvent(s1, eDinv, 0);
    mma_gemm_kernel<HID, 2, 4, false><<<gemmGrid, 256, 0, s1>>>(x, w1hi, w1lo, nullptr, dinv, h1, NN, IND);
    cudaEventRecord(eGemm1, s1);

    // ---- main: finish CSR ----
    scan_offsets_kernel<<<1, 32>>>(bsum, boff, rowptr, NN);
    scan_write_kernel<<<SC_NB, SC_T>>>(deg, boff, rowptr, fill, NN);
    fill_kernel<<<(E + 255) / 256, 256>>>(src, dst, fill, csrc, E);

    // ---- join, then the serial tail ----
    cudaStreamWaitEvent(0, eGemm1, 0);
    gather128_kernel<<<warpsGrid, 256>>>((const float4*)h1, csrc, rowptr, dinv, (float4*)agg1);
    mma_gemm_kernel<OUTD, 4, 2, true><<<gemmGrid, 256>>>(agg1, w2hi, w2lo, b1, dinv, h2, NN, HID);
    gather64_kernel<<<warpsGrid, 256>>>((const float2*)h2, csrc, rowptr, dinv, b2, (float2*)out);
}